// round 9
// baseline (speedup 1.0000x reference)
#include <cuda_runtime.h>
#include <cuda_bf16.h>
#include <cstdint>
#include <cstddef>

#define FDIM 64
#define EMAX 1600000
#define NPART 64

// ---------------- device scratch (no allocations allowed) ----------------
__device__ float g_bufA[(size_t)EMAX * FDIM];   // 409.6 MB
__device__ float g_bufB[(size_t)EMAX * FDIM];   // 409.6 MB
__device__ float g_part[NPART * 2 * FDIM];      // partial stats buckets
__device__ __align__(16) float g_sums[2 * FDIM];
__device__ __align__(16) float g_scale[FDIM];   // gamma * rstd
__device__ __align__(16) float g_shift[FDIM];   // beta - mu * gamma * rstd

// softplus(x) = max(x,0) + log1p(exp(-|x|)); __logf(1+e) abs err < 6e-8.
__device__ __forceinline__ float softplusf(float x) {
    float e = __expf(-fabsf(x));
    return fmaxf(x, 0.0f) + __logf(1.0f + e);
}

// split (x,y) into bf16 hi pack + bf16 residual pack (x in low half)
__device__ __forceinline__ void split2(float x, float y, uint32_t& hi, uint32_t& lo) {
    __nv_bfloat16 hx = __float2bfloat16_rn(x);
    __nv_bfloat16 hy = __float2bfloat16_rn(y);
    float rx = x - __bfloat162float(hx);
    float ry = y - __bfloat162float(hy);
    __nv_bfloat162 h; h.x = hx; h.y = hy;
    __nv_bfloat162 r = __floats2bfloat162_rn(rx, ry);
    hi = *reinterpret_cast<uint32_t*>(&h);
    lo = *reinterpret_cast<uint32_t*>(&r);
}

__device__ __forceinline__ void mma_bf16(float* c, uint32_t a0, uint32_t a1,
                                         uint32_t a2, uint32_t a3,
                                         uint32_t b0, uint32_t b1) {
    asm volatile(
        "mma.sync.aligned.m16n8k16.row.col.f32.bf16.bf16.f32 "
        "{%0,%1,%2,%3}, {%4,%5,%6,%7}, {%8,%9}, {%0,%1,%2,%3};"
        : "+f"(c[0]), "+f"(c[1]), "+f"(c[2]), "+f"(c[3])
        : "r"(a0), "r"(a1), "r"(a2), "r"(a3), "r"(b0), "r"(b1));
}

// ---------------- init: zero output + partial stats ----------------
__global__ void init_kernel(float* __restrict__ out, int n) {
    int i = blockIdx.x * blockDim.x + threadIdx.x;
    if (i < n) out[i] = 0.0f;
    if (i < NPART * 2 * FDIM) g_part[i] = 0.0f;
}

// ---------------- fused GEMM (bf16x2-split mma.sync.m16n8k16) ----------------
// CTA: 256 thr = 8 warps, tile 256 rows x 64 cols, K=64. Warp owns 32 rows
// (2 m-tiles). A fragments live in registers (gmem -> transform -> split -> mma);
// only W goes through smem (staged once, hi/lo pre-split). ~3x less smem traffic.
template<bool ACT>
__device__ __forceinline__ void gemm_body(
    const float* __restrict__ in, float* __restrict__ out,
    const float* __restrict__ W, const float* __restrict__ bias)
{
    __shared__ uint4 sW[1024];       // 16 KB: [s(4)][j(8)][l(32)] = bh0,bh1,bl0,bl1
    __shared__ float sSc[FDIM], sSh[FDIM];

    const int t  = threadIdx.x;
    const int wb = t >> 5;          // warp 0..7
    const int l  = t & 31;
    const int lq = l & 3;           // threadID_in_group
    const int lg = l >> 2;          // groupID

    if (ACT && t < 64) { sSc[t] = g_scale[t]; sSh[t] = g_shift[t]; }

    // W frags: warp wb covers n-tile j = wb, its lane slot, all 4 k-steps.
    {
        const int n = wb * 8 + lg;
        #pragma unroll
        for (int s = 0; s < 4; s++) {
            int k0 = 16 * s + 2 * lq;
            float w00 = W[k0 * 64 + n],       w01 = W[(k0 + 1) * 64 + n];
            float w10 = W[(k0 + 8) * 64 + n], w11 = W[(k0 + 9) * 64 + n];
            uint32_t bh0, bl0, bh1, bl1;
            split2(w00, w01, bh0, bl0);
            split2(w10, w11, bh1, bl1);
            sW[(s * 8 + wb) * 32 + l] = make_uint4(bh0, bh1, bl0, bl1);
        }
    }
    __syncthreads();

    const size_t rowBase = (size_t)blockIdx.x * 256;
    const float* inB = in + rowBase * FDIM;

    float acc[2][8][4];
    #pragma unroll
    for (int mt = 0; mt < 2; mt++)
        #pragma unroll
        for (int j = 0; j < 8; j++)
            #pragma unroll
            for (int c = 0; c < 4; c++) acc[mt][j][c] = 0.0f;

    #pragma unroll
    for (int s = 0; s < 4; s++) {
        const int k0 = 16 * s + 2 * lq;
        float sc0, sh0, sc1, sh1, sc8, sh8, sc9, sh9;
        if (ACT) {
            sc0 = sSc[k0];     sh0 = sSh[k0];
            sc1 = sSc[k0 + 1]; sh1 = sSh[k0 + 1];
            sc8 = sSc[k0 + 8]; sh8 = sSh[k0 + 8];
            sc9 = sSc[k0 + 9]; sh9 = sSh[k0 + 9];
        }
        uint4 ah[2], al[2];
        #pragma unroll
        for (int mt = 0; mt < 2; mt++) {
            const int rA = wb * 32 + mt * 16 + lg;
            const int rB = rA + 8;
            float2 v00 = *reinterpret_cast<const float2*>(inB + (size_t)rA * FDIM + k0);
            float2 v20 = *reinterpret_cast<const float2*>(inB + (size_t)rA * FDIM + k0 + 8);
            float2 v10 = *reinterpret_cast<const float2*>(inB + (size_t)rB * FDIM + k0);
            float2 v30 = *reinterpret_cast<const float2*>(inB + (size_t)rB * FDIM + k0 + 8);
            if (ACT) {
                v00.x = softplusf(fmaf(v00.x, sc0, sh0)); v00.y = softplusf(fmaf(v00.y, sc1, sh1));
                v10.x = softplusf(fmaf(v10.x, sc0, sh0)); v10.y = softplusf(fmaf(v10.y, sc1, sh1));
                v20.x = softplusf(fmaf(v20.x, sc8, sh8)); v20.y = softplusf(fmaf(v20.y, sc9, sh9));
                v30.x = softplusf(fmaf(v30.x, sc8, sh8)); v30.y = softplusf(fmaf(v30.y, sc9, sh9));
            }
            uint32_t a0h, a0l, a1h, a1l, a2h, a2l, a3h, a3l;
            split2(v00.x, v00.y, a0h, a0l);
            split2(v10.x, v10.y, a1h, a1l);
            split2(v20.x, v20.y, a2h, a2l);
            split2(v30.x, v30.y, a3h, a3l);
            ah[mt] = make_uint4(a0h, a1h, a2h, a3h);
            al[mt] = make_uint4(a0l, a1l, a2l, a3l);
        }
        #pragma unroll
        for (int j = 0; j < 8; j++) {
            uint4 w = sW[(s * 8 + j) * 32 + l];
            #pragma unroll
            for (int mt = 0; mt < 2; mt++) {
                mma_bf16(acc[mt][j], ah[mt].x, ah[mt].y, ah[mt].z, ah[mt].w, w.x, w.y);
                mma_bf16(acc[mt][j], al[mt].x, al[mt].y, al[mt].z, al[mt].w, w.x, w.y);
                mma_bf16(acc[mt][j], ah[mt].x, ah[mt].y, ah[mt].z, ah[mt].w, w.z, w.w);
            }
        }
    }

    // ---- epilogue: +bias, store, column stats ----
    __syncthreads();                        // all sW reads done; reuse for stats
    float* sStats = reinterpret_cast<float*>(sW);
    if (t < 128) sStats[t] = 0.0f;

    float st1[16], st2[16];
    #pragma unroll
    for (int i = 0; i < 16; i++) { st1[i] = 0.0f; st2[i] = 0.0f; }

    float* outB = out + rowBase * FDIM;
    #pragma unroll
    for (int mt = 0; mt < 2; mt++) {
        const int rA = wb * 32 + mt * 16 + lg;
        const int rB = rA + 8;
        #pragma unroll
        for (int j = 0; j < 8; j++) {
            int c0 = j * 8 + lq * 2;
            float2 b2 = *reinterpret_cast<const float2*>(bias + c0);
            float y00 = acc[mt][j][0] + b2.x, y01 = acc[mt][j][1] + b2.y;   // row rA
            float y10 = acc[mt][j][2] + b2.x, y11 = acc[mt][j][3] + b2.y;   // row rB
            st1[j * 2]     += y00 + y10;
            st1[j * 2 + 1] += y01 + y11;
            st2[j * 2]     = fmaf(y00, y00, fmaf(y10, y10, st2[j * 2]));
            st2[j * 2 + 1] = fmaf(y01, y01, fmaf(y11, y11, st2[j * 2 + 1]));
            *reinterpret_cast<float2*>(outB + (size_t)rA * FDIM + c0) = make_float2(y00, y01);
            *reinterpret_cast<float2*>(outB + (size_t)rB * FDIM + c0) = make_float2(y10, y11);
        }
    }
    // reduce over the 8 lanes sharing lq (xor 4, 8, 16)
    #pragma unroll
    for (int d = 4; d <= 16; d <<= 1) {
        #pragma unroll
        for (int i = 0; i < 16; i++) {
            st1[i] += __shfl_xor_sync(0xffffffffu, st1[i], d);
            st2[i] += __shfl_xor_sync(0xffffffffu, st2[i], d);
        }
    }
    __syncthreads();                        // sStats zeroed before atomics
    if (lg == 0) {   // lanes 0..3 hold column sums
        #pragma unroll
        for (int j = 0; j < 8; j++) {
            int c0 = j * 8 + lq * 2;
            atomicAdd(&sStats[c0],          st1[j * 2]);
            atomicAdd(&sStats[c0 + 1],      st1[j * 2 + 1]);
            atomicAdd(&sStats[64 + c0],     st2[j * 2]);
            atomicAdd(&sStats[64 + c0 + 1], st2[j * 2 + 1]);
        }
    }
    __syncthreads();
    if (t < 128)
        atomicAdd(&g_part[(blockIdx.x & (NPART - 1)) * 128 + t], sStats[t]);
}

__global__ void __launch_bounds__(256)
gemm0_kernel(const float* __restrict__ in, const float* __restrict__ W,
             const float* __restrict__ bias) {
    gemm_body<false>(in, g_bufA, W, bias);
}
__global__ void __launch_bounds__(256)
gemm1_kernel(const float* __restrict__ W, const float* __restrict__ bias) {
    gemm_body<true>(g_bufA, g_bufB, W, bias);
}
__global__ void __launch_bounds__(256)
gemm2_kernel(const float* __restrict__ W, const float* __restrict__ bias) {
    gemm_body<true>(g_bufB, g_bufA, W, bias);
}

// ---------------- finalize: reduce partials -> scale/shift; re-zero partials ----
__global__ void finalize_kernel(const float* __restrict__ gamma,
                                const float* __restrict__ beta, float invE) {
    int t = threadIdx.x;   // 128 threads
    float tot = 0.0f;
    #pragma unroll 8
    for (int p = 0; p < NPART; p++) {
        tot += g_part[p * 128 + t];
        g_part[p * 128 + t] = 0.0f;
    }
    g_sums[t] = tot;
    __syncthreads();
    if (t < 64) {
        float mu  = g_sums[t] * invE;
        float var = fmaxf(g_sums[64 + t] * invE - mu * mu, 0.0f);
        float rstd = rsqrtf(var + 1e-5f);
        float sc = gamma[t] * rstd;
        g_scale[t] = sc;
        g_shift[t] = fmaf(-mu, sc, beta[t]);
    }
}

// ---------------- final: BN+softplus, dot w_out, edge dir, scatter-add ----------------
__global__ void __launch_bounds__(256)
force_kernel(const float* __restrict__ w_out, const float* __restrict__ b_out,
             const float* __restrict__ pos, const float* __restrict__ nbr,
             const int* __restrict__ eidx, float* __restrict__ out, int E)
{
    __shared__ float sw[FDIM], sc[FDIM], sh[FDIM];
    int t = threadIdx.x;
    if (t < FDIM) { sw[t] = w_out[t]; sc[t] = g_scale[t]; sh[t] = g_shift[t]; }
    __syncthreads();
    int e = blockIdx.x * blockDim.x + t;
    if (e >= E) return;

    const float4* hp = reinterpret_cast<const float4*>(g_bufA + (size_t)e * FDIM);
    float s = 0.0f;
    #pragma unroll
    for (int i = 0; i < 16; i++) {
        float4 v = hp[i];
        int c = i * 4;
        s += softplusf(fmaf(v.x, sc[c + 0], sh[c + 0])) * sw[c + 0];
        s += softplusf(fmaf(v.y, sc[c + 1], sh[c + 1])) * sw[c + 1];
        s += softplusf(fmaf(v.z, sc[c + 2], sh[c + 2])) * sw[c + 2];
        s += softplusf(fmaf(v.w, sc[c + 3], sh[c + 3])) * sw[c + 3];
    }
    s += b_out[0];

    int jn  = eidx[e];          // source j
    int in_ = eidx[E + e];      // target i
    float dx = pos[in_ * 3 + 0] + nbr[(size_t)e * 3 + 0] - pos[jn * 3 + 0];
    float dy = pos[in_ * 3 + 1] + nbr[(size_t)e * 3 + 1] - pos[jn * 3 + 1];
    float dz = pos[in_ * 3 + 2] + nbr[(size_t)e * 3 + 2] - pos[jn * 3 + 2];
    float inv = rsqrtf(fmaf(dx, dx, fmaf(dy, dy, dz * dz)));
    float f = s * inv;
    atomicAdd(out + in_ * 3 + 0, f * dx);
    atomicAdd(out + in_ * 3 + 1, f * dy);
    atomicAdd(out + in_ * 3 + 2, f * dz);
}

// ---------------- launch ----------------
extern "C" void kernel_launch(void* const* d_in, const int* in_sizes, int n_in,
                              void* d_out, int out_size)
{
    const float* edge_attr = (const float*)d_in[0];
    const float* nbr_shift = (const float*)d_in[1];
    const float* pos       = (const float*)d_in[2];
    const float* Ws        = (const float*)d_in[3];   // [3][64][64]
    const float* bs        = (const float*)d_in[4];   // [3][64]
    const float* gammas    = (const float*)d_in[5];   // [3][64]
    const float* betas     = (const float*)d_in[6];   // [3][64]
    const float* w_out     = (const float*)d_in[7];   // [64]
    const float* b_out     = (const float*)d_in[8];   // [1]
    const int*   eidx      = (const int*)d_in[9];     // [2][E] int32
    float* out = (float*)d_out;

    int E = in_sizes[0] / FDIM;     // 1,600,000
    if (E <= 0) return;
    float invE = 1.0f / (float)E;
    int gBlocks = E / 256;          // 6250

    init_kernel<<<(out_size + 255) / 256, 256>>>(out, out_size);

    gemm0_kernel<<<gBlocks, 256>>>(edge_attr, Ws, bs);
    finalize_kernel<<<1, 128>>>(gammas, betas, invE);

    gemm1_kernel<<<gBlocks, 256>>>(Ws + FDIM * FDIM, bs + FDIM);
    finalize_kernel<<<1, 128>>>(gammas + FDIM, betas + FDIM, invE);

    gemm2_kernel<<<gBlocks, 256>>>(Ws + 2 * FDIM * FDIM, bs + 2 * FDIM);
    finalize_kernel<<<1, 128>>>(gammas + 2 * FDIM, betas + 2 * FDIM, invE);

    force_kernel<<<(E + 255) / 256, 256>>>(w_out, b_out, pos, nbr_shift, eidx, out, E);
}

// round 10
// speedup vs baseline: 1.0196x; 1.0196x over previous
#include <cuda_runtime.h>
#include <cuda_bf16.h>
#include <cstdint>
#include <cstddef>

#define FDIM 64
#define EMAX 1600000
#define NPART 64

// ---------------- device scratch (no allocations allowed) ----------------
__device__ float g_bufA[(size_t)EMAX * FDIM];   // 409.6 MB
__device__ float g_bufB[(size_t)EMAX * FDIM];   // 409.6 MB
__device__ float g_part[NPART * 2 * FDIM];      // partial stats buckets
__device__ __align__(16) float g_sums[2 * FDIM];
__device__ __align__(16) float g_scale[FDIM];   // gamma * rstd
__device__ __align__(16) float g_shift[FDIM];   // beta - mu * gamma * rstd

// softplus(x) = max(x,0) + log1p(exp(-|x|)); __logf(1+e) abs err < 6e-8.
__device__ __forceinline__ float softplusf(float x) {
    float e = __expf(-fabsf(x));
    return fmaxf(x, 0.0f) + __logf(1.0f + e);
}

// split (x,y) into bf16 hi pack + bf16 residual pack (x in low half)
__device__ __forceinline__ void split2(float x, float y, uint32_t& hi, uint32_t& lo) {
    __nv_bfloat16 hx = __float2bfloat16_rn(x);
    __nv_bfloat16 hy = __float2bfloat16_rn(y);
    float rx = x - __bfloat162float(hx);
    float ry = y - __bfloat162float(hy);
    __nv_bfloat162 h; h.x = hx; h.y = hy;
    __nv_bfloat162 r = __floats2bfloat162_rn(rx, ry);
    hi = *reinterpret_cast<uint32_t*>(&h);
    lo = *reinterpret_cast<uint32_t*>(&r);
}

__device__ __forceinline__ void mma_bf16(float* c, uint32_t a0, uint32_t a1,
                                         uint32_t a2, uint32_t a3,
                                         uint32_t b0, uint32_t b1) {
    asm volatile(
        "mma.sync.aligned.m16n8k16.row.col.f32.bf16.bf16.f32 "
        "{%0,%1,%2,%3}, {%4,%5,%6,%7}, {%8,%9}, {%0,%1,%2,%3};"
        : "+f"(c[0]), "+f"(c[1]), "+f"(c[2]), "+f"(c[3])
        : "r"(a0), "r"(a1), "r"(a2), "r"(a3), "r"(b0), "r"(b1));
}

// ---------------- init: zero output + partial stats ----------------
__global__ void init_kernel(float* __restrict__ out, int n) {
    int i = blockIdx.x * blockDim.x + threadIdx.x;
    if (i < n) out[i] = 0.0f;
    if (i < NPART * 2 * FDIM) g_part[i] = 0.0f;
}

// ---------------- fused GEMM (bf16x2-split mma.sync.m16n8k16) ----------------
// CTA: 256 thr = 8 warps, tile 128 rows x 64 cols, K=64. Warp wb owns rows
// 16wb..16wb+15 (1 m-tile -> 32 acc regs). A fragments loaded gmem->reg with
// transform+split in registers (NO smem round-trip); W staged once in smem.
template<bool ACT>
__device__ __forceinline__ void gemm_body(
    const float* __restrict__ in, float* __restrict__ out,
    const float* __restrict__ W, const float* __restrict__ bias)
{
    __shared__ uint4 sW[1024];       // 16 KB: [s(4)][j(8)][l(32)] = bh0,bh1,bl0,bl1
    __shared__ float sSc[FDIM], sSh[FDIM];

    const int t  = threadIdx.x;
    const int wb = t >> 5;          // warp 0..7
    const int l  = t & 31;
    const int lq = l & 3;           // threadID_in_group
    const int lg = l >> 2;          // groupID

    if (ACT && t < 64) { sSc[t] = g_scale[t]; sSh[t] = g_shift[t]; }

    // W frags: warp wb covers n-tile j = wb, its lane slot, all 4 k-steps.
    {
        const int n = wb * 8 + lg;
        #pragma unroll
        for (int s = 0; s < 4; s++) {
            int k0 = 16 * s + 2 * lq;
            float w00 = W[k0 * 64 + n],       w01 = W[(k0 + 1) * 64 + n];
            float w10 = W[(k0 + 8) * 64 + n], w11 = W[(k0 + 9) * 64 + n];
            uint32_t bh0, bl0, bh1, bl1;
            split2(w00, w01, bh0, bl0);
            split2(w10, w11, bh1, bl1);
            sW[(s * 8 + wb) * 32 + l] = make_uint4(bh0, bh1, bl0, bl1);
        }
    }
    __syncthreads();

    const size_t rowBase = (size_t)blockIdx.x * 128;
    const float* inB = in + rowBase * FDIM;
    const int r0 = wb * 16 + lg;    // this thread's m-tile rows
    const int r1 = r0 + 8;

    float acc[8][4];
    #pragma unroll
    for (int j = 0; j < 8; j++)
        #pragma unroll
        for (int c = 0; c < 4; c++) acc[j][c] = 0.0f;

    #pragma unroll
    for (int s = 0; s < 4; s++) {
        const int k0 = 16 * s + 2 * lq;
        // A frags straight from gmem (float2 pairs), transform + split in regs
        float2 v00 = *reinterpret_cast<const float2*>(inB + (size_t)r0 * FDIM + k0);
        float2 v20 = *reinterpret_cast<const float2*>(inB + (size_t)r0 * FDIM + k0 + 8);
        float2 v10 = *reinterpret_cast<const float2*>(inB + (size_t)r1 * FDIM + k0);
        float2 v30 = *reinterpret_cast<const float2*>(inB + (size_t)r1 * FDIM + k0 + 8);
        if (ACT) {
            float sc0 = sSc[k0],     sh0 = sSh[k0];
            float sc1 = sSc[k0 + 1], sh1 = sSh[k0 + 1];
            float sc8 = sSc[k0 + 8], sh8 = sSh[k0 + 8];
            float sc9 = sSc[k0 + 9], sh9 = sSh[k0 + 9];
            v00.x = softplusf(fmaf(v00.x, sc0, sh0)); v00.y = softplusf(fmaf(v00.y, sc1, sh1));
            v10.x = softplusf(fmaf(v10.x, sc0, sh0)); v10.y = softplusf(fmaf(v10.y, sc1, sh1));
            v20.x = softplusf(fmaf(v20.x, sc8, sh8)); v20.y = softplusf(fmaf(v20.y, sc9, sh9));
            v30.x = softplusf(fmaf(v30.x, sc8, sh8)); v30.y = softplusf(fmaf(v30.y, sc9, sh9));
        }
        uint32_t a0h, a0l, a1h, a1l, a2h, a2l, a3h, a3l;
        split2(v00.x, v00.y, a0h, a0l);   // row r0, k k0..k0+1
        split2(v10.x, v10.y, a1h, a1l);   // row r1
        split2(v20.x, v20.y, a2h, a2l);   // row r0, k+8
        split2(v30.x, v30.y, a3h, a3l);   // row r1, k+8
        #pragma unroll
        for (int j = 0; j < 8; j++) {
            uint4 w = sW[(s * 8 + j) * 32 + l];
            mma_bf16(acc[j], a0h, a1h, a2h, a3h, w.x, w.y);
            mma_bf16(acc[j], a0l, a1l, a2l, a3l, w.x, w.y);
            mma_bf16(acc[j], a0h, a1h, a2h, a3h, w.z, w.w);
        }
    }

    // ---- epilogue: +bias, store, column stats (R7-proven layout) ----
    __syncthreads();                        // all sW reads done; reuse for stats
    float* sStats = reinterpret_cast<float*>(sW);
    if (t < 128) sStats[t] = 0.0f;

    float st1[16], st2[16];
    #pragma unroll
    for (int i = 0; i < 16; i++) { st1[i] = 0.0f; st2[i] = 0.0f; }

    float* outB = out + rowBase * FDIM;
    #pragma unroll
    for (int j = 0; j < 8; j++) {
        int c0 = j * 8 + lq * 2;
        float2 b2 = *reinterpret_cast<const float2*>(bias + c0);
        float y00 = acc[j][0] + b2.x, y01 = acc[j][1] + b2.y;   // row r0
        float y10 = acc[j][2] + b2.x, y11 = acc[j][3] + b2.y;   // row r1
        st1[j * 2]     += y00 + y10;
        st1[j * 2 + 1] += y01 + y11;
        st2[j * 2]     = fmaf(y00, y00, fmaf(y10, y10, st2[j * 2]));
        st2[j * 2 + 1] = fmaf(y01, y01, fmaf(y11, y11, st2[j * 2 + 1]));
        *reinterpret_cast<float2*>(outB + (size_t)r0 * FDIM + c0) = make_float2(y00, y01);
        *reinterpret_cast<float2*>(outB + (size_t)r1 * FDIM + c0) = make_float2(y10, y11);
    }
    // reduce over the 8 lanes sharing lq (xor 4, 8, 16)
    #pragma unroll
    for (int d = 4; d <= 16; d <<= 1) {
        #pragma unroll
        for (int i = 0; i < 16; i++) {
            st1[i] += __shfl_xor_sync(0xffffffffu, st1[i], d);
            st2[i] += __shfl_xor_sync(0xffffffffu, st2[i], d);
        }
    }
    __syncthreads();                        // sStats zeroed before atomics
    if (lg == 0) {   // lanes 0..3 hold column sums
        #pragma unroll
        for (int j = 0; j < 8; j++) {
            int c0 = j * 8 + lq * 2;
            atomicAdd(&sStats[c0],          st1[j * 2]);
            atomicAdd(&sStats[c0 + 1],      st1[j * 2 + 1]);
            atomicAdd(&sStats[64 + c0],     st2[j * 2]);
            atomicAdd(&sStats[64 + c0 + 1], st2[j * 2 + 1]);
        }
    }
    __syncthreads();
    if (t < 128)
        atomicAdd(&g_part[(blockIdx.x & (NPART - 1)) * 128 + t], sStats[t]);
}

__global__ void __launch_bounds__(256, 3)
gemm0_kernel(const float* __restrict__ in, const float* __restrict__ W,
             const float* __restrict__ bias) {
    gemm_body<false>(in, g_bufA, W, bias);
}
__global__ void __launch_bounds__(256, 3)
gemm1_kernel(const float* __restrict__ W, const float* __restrict__ bias) {
    gemm_body<true>(g_bufA, g_bufB, W, bias);
}
__global__ void __launch_bounds__(256, 3)
gemm2_kernel(const float* __restrict__ W, const float* __restrict__ bias) {
    gemm_body<true>(g_bufB, g_bufA, W, bias);
}

// ---------------- finalize: reduce partials -> scale/shift; re-zero partials ----
__global__ void finalize_kernel(const float* __restrict__ gamma,
                                const float* __restrict__ beta, float invE) {
    int t = threadIdx.x;   // 128 threads
    float tot = 0.0f;
    #pragma unroll 8
    for (int p = 0; p < NPART; p++) {
        tot += g_part[p * 128 + t];
        g_part[p * 128 + t] = 0.0f;
    }
    g_sums[t] = tot;
    __syncthreads();
    if (t < 64) {
        float mu  = g_sums[t] * invE;
        float var = fmaxf(g_sums[64 + t] * invE - mu * mu, 0.0f);
        float rstd = rsqrtf(var + 1e-5f);
        float sc = gamma[t] * rstd;
        g_scale[t] = sc;
        g_shift[t] = fmaf(-mu, sc, beta[t]);
    }
}

// ---------------- final: BN+softplus, dot w_out, edge dir, scatter-add ----------------
__global__ void __launch_bounds__(256)
force_kernel(const float* __restrict__ w_out, const float* __restrict__ b_out,
             const float* __restrict__ pos, const float* __restrict__ nbr,
             const int* __restrict__ eidx, float* __restrict__ out, int E)
{
    __shared__ float sw[FDIM], sc[FDIM], sh[FDIM];
    int t = threadIdx.x;
    if (t < FDIM) { sw[t] = w_out[t]; sc[t] = g_scale[t]; sh[t] = g_shift[t]; }
    __syncthreads();
    int e = blockIdx.x * blockDim.x + t;
    if (e >= E) return;

    const float4* hp = reinterpret_cast<const float4*>(g_bufA + (size_t)e * FDIM);
    float s = 0.0f;
    #pragma unroll
    for (int i = 0; i < 16; i++) {
        float4 v = hp[i];
        int c = i * 4;
        s += softplusf(fmaf(v.x, sc[c + 0], sh[c + 0])) * sw[c + 0];
        s += softplusf(fmaf(v.y, sc[c + 1], sh[c + 1])) * sw[c + 1];
        s += softplusf(fmaf(v.z, sc[c + 2], sh[c + 2])) * sw[c + 2];
        s += softplusf(fmaf(v.w, sc[c + 3], sh[c + 3])) * sw[c + 3];
    }
    s += b_out[0];

    int jn  = eidx[e];          // source j
    int in_ = eidx[E + e];      // target i
    float dx = pos[in_ * 3 + 0] + nbr[(size_t)e * 3 + 0] - pos[jn * 3 + 0];
    float dy = pos[in_ * 3 + 1] + nbr[(size_t)e * 3 + 1] - pos[jn * 3 + 1];
    float dz = pos[in_ * 3 + 2] + nbr[(size_t)e * 3 + 2] - pos[jn * 3 + 2];
    float inv = rsqrtf(fmaf(dx, dx, fmaf(dy, dy, dz * dz)));
    float f = s * inv;
    atomicAdd(out + in_ * 3 + 0, f * dx);
    atomicAdd(out + in_ * 3 + 1, f * dy);
    atomicAdd(out + in_ * 3 + 2, f * dz);
}

// ---------------- launch ----------------
extern "C" void kernel_launch(void* const* d_in, const int* in_sizes, int n_in,
                              void* d_out, int out_size)
{
    const float* edge_attr = (const float*)d_in[0];
    const float* nbr_shift = (const float*)d_in[1];
    const float* pos       = (const float*)d_in[2];
    const float* Ws        = (const float*)d_in[3];   // [3][64][64]
    const float* bs        = (const float*)d_in[4];   // [3][64]
    const float* gammas    = (const float*)d_in[5];   // [3][64]
    const float* betas     = (const float*)d_in[6];   // [3][64]
    const float* w_out     = (const float*)d_in[7];   // [64]
    const float* b_out     = (const float*)d_in[8];   // [1]
    const int*   eidx      = (const int*)d_in[9];     // [2][E] int32
    float* out = (float*)d_out;

    int E = in_sizes[0] / FDIM;     // 1,600,000
    if (E <= 0) return;
    float invE = 1.0f / (float)E;
    int gBlocks = E / 128;          // 12500

    init_kernel<<<(out_size + 255) / 256, 256>>>(out, out_size);

    gemm0_kernel<<<gBlocks, 256>>>(edge_attr, Ws, bs);
    finalize_kernel<<<1, 128>>>(gammas, betas, invE);

    gemm1_kernel<<<gBlocks, 256>>>(Ws + FDIM * FDIM, bs + FDIM);
    finalize_kernel<<<1, 128>>>(gammas + FDIM, betas + FDIM, invE);

    gemm2_kernel<<<gBlocks, 256>>>(Ws + 2 * FDIM * FDIM, bs + 2 * FDIM);
    finalize_kernel<<<1, 128>>>(gammas + 2 * FDIM, betas + 2 * FDIM, invE);

    force_kernel<<<(E + 255) / 256, 256>>>(w_out, b_out, pos, nbr_shift, eidx, out, E);
}

// round 12
// speedup vs baseline: 1.2903x; 1.2656x over previous
#include <cuda_runtime.h>
#include <cuda_bf16.h>
#include <cstdint>
#include <cstddef>

#define FDIM 64
#define EMAX 1600000
#define NPART 64

// ---------------- device scratch (no allocations allowed) ----------------
// Activation buffers hold FRAGMENT-MAJOR float4s:
//   index ((blk*8 + wb)*8 + j)*32 + l  holds (y(r0,c), y(r0,c+1), y(r1,c), y(r1,c+1))
//   with r0 = blk*128 + wb*16 + (l>>2), r1 = r0 + 8, c = j*8 + (l&3)*2.
__device__ float g_bufA[(size_t)EMAX * FDIM];   // 409.6 MB
__device__ float g_bufB[(size_t)EMAX * FDIM];   // 409.6 MB
__device__ float g_part[NPART * 2 * FDIM];      // partial stats buckets
__device__ __align__(16) float g_sums[2 * FDIM];
__device__ __align__(16) float g_scale[FDIM];   // gamma * rstd
__device__ __align__(16) float g_shift[FDIM];   // beta - mu * gamma * rstd

// softplus(x) = max(x,0) + log1p(exp(-|x|)); __logf(1+e) abs err < 6e-8.
__device__ __forceinline__ float softplusf(float x) {
    float e = __expf(-fabsf(x));
    return fmaxf(x, 0.0f) + __logf(1.0f + e);
}

// split (x,y) into bf16 hi pack + bf16 residual pack (x in low half)
__device__ __forceinline__ void split2(float x, float y, uint32_t& hi, uint32_t& lo) {
    __nv_bfloat16 hx = __float2bfloat16_rn(x);
    __nv_bfloat16 hy = __float2bfloat16_rn(y);
    float rx = x - __bfloat162float(hx);
    float ry = y - __bfloat162float(hy);
    __nv_bfloat162 h; h.x = hx; h.y = hy;
    __nv_bfloat162 r = __floats2bfloat162_rn(rx, ry);
    hi = *reinterpret_cast<uint32_t*>(&h);
    lo = *reinterpret_cast<uint32_t*>(&r);
}

__device__ __forceinline__ void mma_bf16(float* c, uint32_t a0, uint32_t a1,
                                         uint32_t a2, uint32_t a3,
                                         uint32_t b0, uint32_t b1) {
    asm volatile(
        "mma.sync.aligned.m16n8k16.row.col.f32.bf16.bf16.f32 "
        "{%0,%1,%2,%3}, {%4,%5,%6,%7}, {%8,%9}, {%0,%1,%2,%3};"
        : "+f"(c[0]), "+f"(c[1]), "+f"(c[2]), "+f"(c[3])
        : "r"(a0), "r"(a1), "r"(a2), "r"(a3), "r"(b0), "r"(b1));
}

// ---------------- init: zero output + partial stats ----------------
__global__ void init_kernel(float* __restrict__ out, int n) {
    int i = blockIdx.x * blockDim.x + threadIdx.x;
    if (i < n) out[i] = 0.0f;
    if (i < NPART * 2 * FDIM) g_part[i] = 0.0f;
}

// ---------------- fused GEMM (bf16x2-split mma.sync.m16n8k16) ----------------
// CTA: 256 thr = 8 warps, tile 128 rows x 64 cols, K=64. Warp wb owns rows
// 16wb..16wb+15. ACT=false: input row-major (edge_attr). ACT=true: input
// FRAGMENT-MAJOR (coalesced LDG.128). Output always fragment-major (coalesced
// STG.128). W staged once in smem hi/lo pre-split.
template<bool ACT>
__device__ __forceinline__ void gemm_body(
    const float* __restrict__ in, float* __restrict__ out,
    const float* __restrict__ W, const float* __restrict__ bias)
{
    __shared__ uint4 sW[1024];       // 16 KB: [s(4)][j(8)][l(32)] = bh0,bh1,bl0,bl1
    __shared__ float sSc[FDIM], sSh[FDIM];

    const int t  = threadIdx.x;
    const int wb = t >> 5;          // warp 0..7
    const int l  = t & 31;
    const int lq = l & 3;           // threadID_in_group
    const int lg = l >> 2;          // groupID

    if (ACT && t < 64) { sSc[t] = g_scale[t]; sSh[t] = g_shift[t]; }

    // W frags: warp wb covers n-tile j = wb, its lane slot, all 4 k-steps.
    {
        const int n = wb * 8 + lg;
        #pragma unroll
        for (int s = 0; s < 4; s++) {
            int k0 = 16 * s + 2 * lq;
            float w00 = W[k0 * 64 + n],       w01 = W[(k0 + 1) * 64 + n];
            float w10 = W[(k0 + 8) * 64 + n], w11 = W[(k0 + 9) * 64 + n];
            uint32_t bh0, bl0, bh1, bl1;
            split2(w00, w01, bh0, bl0);
            split2(w10, w11, bh1, bl1);
            sW[(s * 8 + wb) * 32 + l] = make_uint4(bh0, bh1, bl0, bl1);
        }
    }
    __syncthreads();

    const size_t rowBase = (size_t)blockIdx.x * 128;
    const float* inB = in + rowBase * FDIM;                    // row-major path
    const float4* inF = reinterpret_cast<const float4*>(in);   // frag-major path
    const size_t fbase = ((size_t)blockIdx.x * 8 + wb) * 8;    // frag group base
    const int r0 = wb * 16 + lg;    // this thread's m-tile rows (within CTA tile)
    const int r1 = r0 + 8;

    float acc[8][4];
    #pragma unroll
    for (int j = 0; j < 8; j++)
        #pragma unroll
        for (int c = 0; c < 4; c++) acc[j][c] = 0.0f;

    #pragma unroll
    for (int s = 0; s < 4; s++) {
        const int k0 = 16 * s + 2 * lq;
        float2 v00, v10, v20, v30;
        if (ACT) {
            // coalesced: two float4s hold (r0,r1) x (k0,k0+1) and (k0+8,k0+9)
            float4 fa = inF[(fbase + 2 * s) * 32 + l];
            float4 fb = inF[(fbase + 2 * s + 1) * 32 + l];
            v00 = make_float2(fa.x, fa.y);   // row r0, k0..k0+1
            v10 = make_float2(fa.z, fa.w);   // row r1, k0..k0+1
            v20 = make_float2(fb.x, fb.y);   // row r0, k0+8..k0+9
            v30 = make_float2(fb.z, fb.w);   // row r1, k0+8..k0+9
            float sc0 = sSc[k0],     sh0 = sSh[k0];
            float sc1 = sSc[k0 + 1], sh1 = sSh[k0 + 1];
            float sc8 = sSc[k0 + 8], sh8 = sSh[k0 + 8];
            float sc9 = sSc[k0 + 9], sh9 = sSh[k0 + 9];
            v00.x = softplusf(fmaf(v00.x, sc0, sh0)); v00.y = softplusf(fmaf(v00.y, sc1, sh1));
            v10.x = softplusf(fmaf(v10.x, sc0, sh0)); v10.y = softplusf(fmaf(v10.y, sc1, sh1));
            v20.x = softplusf(fmaf(v20.x, sc8, sh8)); v20.y = softplusf(fmaf(v20.y, sc9, sh9));
            v30.x = softplusf(fmaf(v30.x, sc8, sh8)); v30.y = softplusf(fmaf(v30.y, sc9, sh9));
        } else {
            v00 = *reinterpret_cast<const float2*>(inB + (size_t)r0 * FDIM + k0);
            v20 = *reinterpret_cast<const float2*>(inB + (size_t)r0 * FDIM + k0 + 8);
            v10 = *reinterpret_cast<const float2*>(inB + (size_t)r1 * FDIM + k0);
            v30 = *reinterpret_cast<const float2*>(inB + (size_t)r1 * FDIM + k0 + 8);
        }
        uint32_t a0h, a0l, a1h, a1l, a2h, a2l, a3h, a3l;
        split2(v00.x, v00.y, a0h, a0l);   // row r0, k k0..k0+1
        split2(v10.x, v10.y, a1h, a1l);   // row r1
        split2(v20.x, v20.y, a2h, a2l);   // row r0, k+8
        split2(v30.x, v30.y, a3h, a3l);   // row r1, k+8
        #pragma unroll
        for (int j = 0; j < 8; j++) {
            uint4 w = sW[(s * 8 + j) * 32 + l];
            mma_bf16(acc[j], a0h, a1h, a2h, a3h, w.x, w.y);
            mma_bf16(acc[j], a0l, a1l, a2l, a3l, w.x, w.y);
            mma_bf16(acc[j], a0h, a1h, a2h, a3h, w.z, w.w);
        }
    }

    // ---- epilogue: +bias, coalesced frag-major store, column stats ----
    __syncthreads();                        // all sW reads done; reuse for stats
    float* sStats = reinterpret_cast<float*>(sW);
    if (t < 128) sStats[t] = 0.0f;

    float st1[16], st2[16];
    #pragma unroll
    for (int i = 0; i < 16; i++) { st1[i] = 0.0f; st2[i] = 0.0f; }

    float4* outF = reinterpret_cast<float4*>(out);
    #pragma unroll
    for (int j = 0; j < 8; j++) {
        int c0 = j * 8 + lq * 2;
        float2 b2 = *reinterpret_cast<const float2*>(bias + c0);
        float y00 = acc[j][0] + b2.x, y01 = acc[j][1] + b2.y;   // row r0
        float y10 = acc[j][2] + b2.x, y11 = acc[j][3] + b2.y;   // row r1
        st1[j * 2]     += y00 + y10;
        st1[j * 2 + 1] += y01 + y11;
        st2[j * 2]     = fmaf(y00, y00, fmaf(y10, y10, st2[j * 2]));
        st2[j * 2 + 1] = fmaf(y01, y01, fmaf(y11, y11, st2[j * 2 + 1]));
        outF[(fbase + j) * 32 + l] = make_float4(y00, y01, y10, y11);
    }
    // reduce over the 8 lanes sharing lq (xor 4, 8, 16)
    #pragma unroll
    for (int d = 4; d <= 16; d <<= 1) {
        #pragma unroll
        for (int i = 0; i < 16; i++) {
            st1[i] += __shfl_xor_sync(0xffffffffu, st1[i], d);
            st2[i] += __shfl_xor_sync(0xffffffffu, st2[i], d);
        }
    }
    __syncthreads();                        // sStats zeroed before atomics
    if (lg == 0) {   // lanes 0..3 hold column sums
        #pragma unroll
        for (int j = 0; j < 8; j++) {
            int c0 = j * 8 + lq * 2;
            atomicAdd(&sStats[c0],          st1[j * 2]);
            atomicAdd(&sStats[c0 + 1],      st1[j * 2 + 1]);
            atomicAdd(&sStats[64 + c0],     st2[j * 2]);
            atomicAdd(&sStats[64 + c0 + 1], st2[j * 2 + 1]);
        }
    }
    __syncthreads();
    if (t < 128)
        atomicAdd(&g_part[(blockIdx.x & (NPART - 1)) * 128 + t], sStats[t]);
}

__global__ void __launch_bounds__(256, 3)
gemm0_kernel(const float* __restrict__ in, const float* __restrict__ W,
             const float* __restrict__ bias) {
    gemm_body<false>(in, g_bufA, W, bias);
}
__global__ void __launch_bounds__(256, 3)
gemm1_kernel(const float* __restrict__ W, const float* __restrict__ bias) {
    gemm_body<true>(g_bufA, g_bufB, W, bias);
}
__global__ void __launch_bounds__(256, 3)
gemm2_kernel(const float* __restrict__ W, const float* __restrict__ bias) {
    gemm_body<true>(g_bufB, g_bufA, W, bias);
}

// ---------------- finalize: reduce partials -> scale/shift; re-zero partials ----
__global__ void finalize_kernel(const float* __restrict__ gamma,
                                const float* __restrict__ beta, float invE) {
    int t = threadIdx.x;   // 128 threads
    float tot = 0.0f;
    #pragma unroll 8
    for (int p = 0; p < NPART; p++) {
        tot += g_part[p * 128 + t];
        g_part[p * 128 + t] = 0.0f;
    }
    g_sums[t] = tot;
    __syncthreads();
    if (t < 64) {
        float mu  = g_sums[t] * invE;
        float var = fmaxf(g_sums[64 + t] * invE - mu * mu, 0.0f);
        float rstd = rsqrtf(var + 1e-5f);
        float sc = gamma[t] * rstd;
        g_scale[t] = sc;
        g_shift[t] = fmaf(-mu, sc, beta[t]);
    }
}

// ---------------- final: BN+softplus, dot w_out, edge dir, scatter-add --------
// Consumes FRAGMENT-MAJOR g_bufA with coalesced LDG.128. Thread (wb,l) dots its
// lane's share of rows r0 = blk*128+wb*16+lg and r1 = r0+8; 2-shuffle reduce
// over the 4 lq lanes; lanes lq0/lq1 finalize edges r0/r1.
__global__ void __launch_bounds__(256)
force_kernel(const float* __restrict__ w_out, const float* __restrict__ b_out,
             const float* __restrict__ pos, const float* __restrict__ nbr,
             const int* __restrict__ eidx, float* __restrict__ out, int E)
{
    __shared__ float swv[FDIM], sc[FDIM], sh[FDIM];
    int t = threadIdx.x;
    if (t < FDIM) { swv[t] = w_out[t]; sc[t] = g_scale[t]; sh[t] = g_shift[t]; }
    __syncthreads();

    const int wb = t >> 5;
    const int l  = t & 31;
    const int lq = l & 3;
    const int lg = l >> 2;
    const size_t fbase = ((size_t)blockIdx.x * 8 + wb) * 8;
    const float4* F = reinterpret_cast<const float4*>(g_bufA);

    float s0 = 0.0f, s1 = 0.0f;
    #pragma unroll
    for (int j = 0; j < 8; j++) {
        float4 v = F[(fbase + j) * 32 + l];
        int c = j * 8 + lq * 2;
        float w0 = swv[c], w1 = swv[c + 1];
        float c0s = sc[c], c0h = sh[c], c1s = sc[c + 1], c1h = sh[c + 1];
        s0 = fmaf(softplusf(fmaf(v.x, c0s, c0h)), w0, s0);
        s0 = fmaf(softplusf(fmaf(v.y, c1s, c1h)), w1, s0);
        s1 = fmaf(softplusf(fmaf(v.z, c0s, c0h)), w0, s1);
        s1 = fmaf(softplusf(fmaf(v.w, c1s, c1h)), w1, s1);
    }
    // reduce over lq lanes (xor 1, 2)
    s0 += __shfl_xor_sync(0xffffffffu, s0, 1);
    s0 += __shfl_xor_sync(0xffffffffu, s0, 2);
    s1 += __shfl_xor_sync(0xffffffffu, s1, 1);
    s1 += __shfl_xor_sync(0xffffffffu, s1, 2);

    int e = -1;
    float s = 0.0f;
    if (lq == 0)      { e = blockIdx.x * 128 + wb * 16 + lg;     s = s0; }
    else if (lq == 1) { e = blockIdx.x * 128 + wb * 16 + lg + 8; s = s1; }
    if (e >= 0 && e < E) {
        s += b_out[0];
        int jn  = eidx[e];          // source j
        int in_ = eidx[E + e];      // target i
        float dx = pos[in_ * 3 + 0] + nbr[(size_t)e * 3 + 0] - pos[jn * 3 + 0];
        float dy = pos[in_ * 3 + 1] + nbr[(size_t)e * 3 + 1] - pos[jn * 3 + 1];
        float dz = pos[in_ * 3 + 2] + nbr[(size_t)e * 3 + 2] - pos[jn * 3 + 2];
        float inv = rsqrtf(fmaf(dx, dx, fmaf(dy, dy, dz * dz)));
        float f = s * inv;
        atomicAdd(out + in_ * 3 + 0, f * dx);
        atomicAdd(out + in_ * 3 + 1, f * dy);
        atomicAdd(out + in_ * 3 + 2, f * dz);
    }
}

// ---------------- launch ----------------
extern "C" void kernel_launch(void* const* d_in, const int* in_sizes, int n_in,
                              void* d_out, int out_size)
{
    const float* edge_attr = (const float*)d_in[0];
    const float* nbr_shift = (const float*)d_in[1];
    const float* pos       = (const float*)d_in[2];
    const float* Ws        = (const float*)d_in[3];   // [3][64][64]
    const float* bs        = (const float*)d_in[4];   // [3][64]
    const float* gammas    = (const float*)d_in[5];   // [3][64]
    const float* betas     = (const float*)d_in[6];   // [3][64]
    const float* w_out     = (const float*)d_in[7];   // [64]
    const float* b_out     = (const float*)d_in[8];   // [1]
    const int*   eidx      = (const int*)d_in[9];     // [2][E] int32
    float* out = (float*)d_out;

    int E = in_sizes[0] / FDIM;     // 1,600,000
    if (E <= 0) return;
    float invE = 1.0f / (float)E;
    int gBlocks = E / 128;          // 12500

    init_kernel<<<(out_size + 255) / 256, 256>>>(out, out_size);

    gemm0_kernel<<<gBlocks, 256>>>(edge_attr, Ws, bs);
    finalize_kernel<<<1, 128>>>(gammas, betas, invE);

    gemm1_kernel<<<gBlocks, 256>>>(Ws + FDIM * FDIM, bs + FDIM);
    finalize_kernel<<<1, 128>>>(gammas + FDIM, betas + FDIM, invE);

    gemm2_kernel<<<gBlocks, 256>>>(Ws + 2 * FDIM * FDIM, bs + 2 * FDIM);
    finalize_kernel<<<1, 128>>>(gammas + 2 * FDIM, betas + 2 * FDIM, invE);

    force_kernel<<<gBlocks, 256>>>(w_out, b_out, pos, nbr_shift, eidx, out, E);
}

// round 13
// speedup vs baseline: 1.3947x; 1.0809x over previous
#include <cuda_runtime.h>
#include <cuda_bf16.h>
#include <cstdint>
#include <cstddef>

#define FDIM 64
#define EMAX 1600000
#define NPART 64

// ---------------- device scratch (no allocations allowed) ----------------
// Activation buffers hold FRAGMENT-MAJOR float4s:
//   index ((blk*8 + wb)*8 + j)*32 + l  holds (y(r0,c), y(r0,c+1), y(r1,c), y(r1,c+1))
//   with blk = row/128, r0 = blk*128 + wb*16 + (l>>2), r1 = r0 + 8, c = j*8 + (l&3)*2.
__device__ float g_bufA[(size_t)EMAX * FDIM];   // 409.6 MB
__device__ float g_bufB[(size_t)EMAX * FDIM];   // 409.6 MB
__device__ float g_part[NPART * 2 * FDIM];      // partial stats buckets
__device__ __align__(16) float g_sums[2 * FDIM];
__device__ __align__(16) float g_scale[FDIM];   // gamma * rstd
__device__ __align__(16) float g_shift[FDIM];   // beta - mu * gamma * rstd

// softplus(x) = max(x,0) + log1p(exp(-|x|)); __logf(1+e) abs err < 6e-8.
__device__ __forceinline__ float softplusf(float x) {
    float e = __expf(-fabsf(x));
    return fmaxf(x, 0.0f) + __logf(1.0f + e);
}

// split (x,y) into bf16 hi pack + bf16 residual pack (x in low half)
__device__ __forceinline__ void split2(float x, float y, uint32_t& hi, uint32_t& lo) {
    __nv_bfloat16 hx = __float2bfloat16_rn(x);
    __nv_bfloat16 hy = __float2bfloat16_rn(y);
    float rx = x - __bfloat162float(hx);
    float ry = y - __bfloat162float(hy);
    __nv_bfloat162 h; h.x = hx; h.y = hy;
    __nv_bfloat162 r = __floats2bfloat162_rn(rx, ry);
    hi = *reinterpret_cast<uint32_t*>(&h);
    lo = *reinterpret_cast<uint32_t*>(&r);
}

__device__ __forceinline__ void mma_bf16(float* c, uint32_t a0, uint32_t a1,
                                         uint32_t a2, uint32_t a3,
                                         uint32_t b0, uint32_t b1) {
    asm volatile(
        "mma.sync.aligned.m16n8k16.row.col.f32.bf16.bf16.f32 "
        "{%0,%1,%2,%3}, {%4,%5,%6,%7}, {%8,%9}, {%0,%1,%2,%3};"
        : "+f"(c[0]), "+f"(c[1]), "+f"(c[2]), "+f"(c[3])
        : "r"(a0), "r"(a1), "r"(a2), "r"(a3), "r"(b0), "r"(b1));
}

// ---------------- init: zero output + partial stats ----------------
__global__ void init_kernel(float* __restrict__ out, int n) {
    int i = blockIdx.x * blockDim.x + threadIdx.x;
    if (i < n) out[i] = 0.0f;
    if (i < NPART * 2 * FDIM) g_part[i] = 0.0f;
}

// ---------------- fused GEMM (bf16x2-split mma.sync.m16n8k16) ----------------
// CTA: 256 thr = 8 warps, tile 256 rows x 64 cols (2 m-tiles per warp), K=64.
// One W LDS.128 now feeds 6 mmas (2 m-tiles x 3 split terms) -> per-row L1
// wavefronts drop ~33% vs the 128-row tile. A frags in registers; W staged
// once in smem hi/lo pre-split. launch_bounds(256,2) caps regs at 128.
template<bool ACT>
__device__ __forceinline__ void gemm_body(
    const float* __restrict__ in, float* __restrict__ out,
    const float* __restrict__ W, const float* __restrict__ bias)
{
    __shared__ uint4 sW[1024];       // 16 KB: [s(4)][j(8)][l(32)] = bh0,bh1,bl0,bl1
    __shared__ float sSc[FDIM], sSh[FDIM];

    const int t  = threadIdx.x;
    const int wb = t >> 5;          // warp 0..7
    const int l  = t & 31;
    const int lq = l & 3;           // threadID_in_group
    const int lg = l >> 2;          // groupID

    if (ACT && t < 64) { sSc[t] = g_scale[t]; sSh[t] = g_shift[t]; }

    // W frags: warp wb covers n-tile j = wb, its lane slot, all 4 k-steps.
    {
        const int n = wb * 8 + lg;
        #pragma unroll
        for (int s = 0; s < 4; s++) {
            int k0 = 16 * s + 2 * lq;
            float w00 = W[k0 * 64 + n],       w01 = W[(k0 + 1) * 64 + n];
            float w10 = W[(k0 + 8) * 64 + n], w11 = W[(k0 + 9) * 64 + n];
            uint32_t bh0, bl0, bh1, bl1;
            split2(w00, w01, bh0, bl0);
            split2(w10, w11, bh1, bl1);
            sW[(s * 8 + wb) * 32 + l] = make_uint4(bh0, bh1, bl0, bl1);
        }
    }
    __syncthreads();

    const size_t rowBase = (size_t)blockIdx.x * 256;
    const float* inB = in + rowBase * FDIM;                    // row-major path
    const float4* inF = reinterpret_cast<const float4*>(in);   // frag-major path
    size_t fbase[2];                                           // 128-row layout blocks
    fbase[0] = (((size_t)blockIdx.x * 2 + 0) * 8 + wb) * 8;
    fbase[1] = (((size_t)blockIdx.x * 2 + 1) * 8 + wb) * 8;

    float acc[2][8][4];
    #pragma unroll
    for (int mt = 0; mt < 2; mt++)
        #pragma unroll
        for (int j = 0; j < 8; j++)
            #pragma unroll
            for (int c = 0; c < 4; c++) acc[mt][j][c] = 0.0f;

    #pragma unroll
    for (int s = 0; s < 4; s++) {
        const int k0 = 16 * s + 2 * lq;
        float sc0, sh0, sc1, sh1, sc8, sh8, sc9, sh9;
        if (ACT) {
            sc0 = sSc[k0];     sh0 = sSh[k0];
            sc1 = sSc[k0 + 1]; sh1 = sSh[k0 + 1];
            sc8 = sSc[k0 + 8]; sh8 = sSh[k0 + 8];
            sc9 = sSc[k0 + 9]; sh9 = sSh[k0 + 9];
        }
        uint4 ah[2], al[2];
        #pragma unroll
        for (int mt = 0; mt < 2; mt++) {
            float2 v00, v10, v20, v30;
            if (ACT) {
                // coalesced: two float4s hold (r0,r1) x (k0,k0+1) and (k0+8,k0+9)
                float4 fa = inF[(fbase[mt] + 2 * s) * 32 + l];
                float4 fb = inF[(fbase[mt] + 2 * s + 1) * 32 + l];
                v00 = make_float2(fa.x, fa.y);   // row r0, k0..k0+1
                v10 = make_float2(fa.z, fa.w);   // row r1, k0..k0+1
                v20 = make_float2(fb.x, fb.y);   // row r0, k0+8..k0+9
                v30 = make_float2(fb.z, fb.w);   // row r1, k0+8..k0+9
                v00.x = softplusf(fmaf(v00.x, sc0, sh0)); v00.y = softplusf(fmaf(v00.y, sc1, sh1));
                v10.x = softplusf(fmaf(v10.x, sc0, sh0)); v10.y = softplusf(fmaf(v10.y, sc1, sh1));
                v20.x = softplusf(fmaf(v20.x, sc8, sh8)); v20.y = softplusf(fmaf(v20.y, sc9, sh9));
                v30.x = softplusf(fmaf(v30.x, sc8, sh8)); v30.y = softplusf(fmaf(v30.y, sc9, sh9));
            } else {
                const int r0 = mt * 128 + wb * 16 + lg;
                const int r1 = r0 + 8;
                v00 = *reinterpret_cast<const float2*>(inB + (size_t)r0 * FDIM + k0);
                v20 = *reinterpret_cast<const float2*>(inB + (size_t)r0 * FDIM + k0 + 8);
                v10 = *reinterpret_cast<const float2*>(inB + (size_t)r1 * FDIM + k0);
                v30 = *reinterpret_cast<const float2*>(inB + (size_t)r1 * FDIM + k0 + 8);
            }
            uint32_t a0h, a0l, a1h, a1l, a2h, a2l, a3h, a3l;
            split2(v00.x, v00.y, a0h, a0l);   // row r0, k k0..k0+1
            split2(v10.x, v10.y, a1h, a1l);   // row r1
            split2(v20.x, v20.y, a2h, a2l);   // row r0, k+8
            split2(v30.x, v30.y, a3h, a3l);   // row r1, k+8
            ah[mt] = make_uint4(a0h, a1h, a2h, a3h);
            al[mt] = make_uint4(a0l, a1l, a2l, a3l);
        }
        #pragma unroll
        for (int j = 0; j < 8; j++) {
            uint4 w = sW[(s * 8 + j) * 32 + l];
            #pragma unroll
            for (int mt = 0; mt < 2; mt++) {
                mma_bf16(acc[mt][j], ah[mt].x, ah[mt].y, ah[mt].z, ah[mt].w, w.x, w.y);
                mma_bf16(acc[mt][j], al[mt].x, al[mt].y, al[mt].z, al[mt].w, w.x, w.y);
                mma_bf16(acc[mt][j], ah[mt].x, ah[mt].y, ah[mt].z, ah[mt].w, w.z, w.w);
            }
        }
    }

    // ---- epilogue: +bias, coalesced frag-major store, column stats ----
    __syncthreads();                        // all sW reads done; reuse for stats
    float* sStats = reinterpret_cast<float*>(sW);
    if (t < 128) sStats[t] = 0.0f;

    float st1[16], st2[16];
    #pragma unroll
    for (int i = 0; i < 16; i++) { st1[i] = 0.0f; st2[i] = 0.0f; }

    float4* outF = reinterpret_cast<float4*>(out);
    #pragma unroll
    for (int mt = 0; mt < 2; mt++) {
        #pragma unroll
        for (int j = 0; j < 8; j++) {
            int c0 = j * 8 + lq * 2;
            float2 b2 = *reinterpret_cast<const float2*>(bias + c0);
            float y00 = acc[mt][j][0] + b2.x, y01 = acc[mt][j][1] + b2.y;   // row r0
            float y10 = acc[mt][j][2] + b2.x, y11 = acc[mt][j][3] + b2.y;   // row r1
            st1[j * 2]     += y00 + y10;
            st1[j * 2 + 1] += y01 + y11;
            st2[j * 2]     = fmaf(y00, y00, fmaf(y10, y10, st2[j * 2]));
            st2[j * 2 + 1] = fmaf(y01, y01, fmaf(y11, y11, st2[j * 2 + 1]));
            outF[(fbase[mt] + j) * 32 + l] = make_float4(y00, y01, y10, y11);
        }
    }
    // reduce over the 8 lanes sharing lq (xor 4, 8, 16)
    #pragma unroll
    for (int d = 4; d <= 16; d <<= 1) {
        #pragma unroll
        for (int i = 0; i < 16; i++) {
            st1[i] += __shfl_xor_sync(0xffffffffu, st1[i], d);
            st2[i] += __shfl_xor_sync(0xffffffffu, st2[i], d);
        }
    }
    __syncthreads();                        // sStats zeroed before atomics
    if (lg == 0) {   // lanes 0..3 hold column sums
        #pragma unroll
        for (int j = 0; j < 8; j++) {
            int c0 = j * 8 + lq * 2;
            atomicAdd(&sStats[c0],          st1[j * 2]);
            atomicAdd(&sStats[c0 + 1],      st1[j * 2 + 1]);
            atomicAdd(&sStats[64 + c0],     st2[j * 2]);
            atomicAdd(&sStats[64 + c0 + 1], st2[j * 2 + 1]);
        }
    }
    __syncthreads();
    if (t < 128)
        atomicAdd(&g_part[(blockIdx.x & (NPART - 1)) * 128 + t], sStats[t]);
}

__global__ void __launch_bounds__(256, 2)
gemm0_kernel(const float* __restrict__ in, const float* __restrict__ W,
             const float* __restrict__ bias) {
    gemm_body<false>(in, g_bufA, W, bias);
}
__global__ void __launch_bounds__(256, 2)
gemm1_kernel(const float* __restrict__ W, const float* __restrict__ bias) {
    gemm_body<true>(g_bufA, g_bufB, W, bias);
}
__global__ void __launch_bounds__(256, 2)
gemm2_kernel(const float* __restrict__ W, const float* __restrict__ bias) {
    gemm_body<true>(g_bufB, g_bufA, W, bias);
}

// ---------------- finalize: reduce partials -> scale/shift; re-zero partials ----
__global__ void finalize_kernel(const float* __restrict__ gamma,
                                const float* __restrict__ beta, float invE) {
    int t = threadIdx.x;   // 128 threads
    float tot = 0.0f;
    #pragma unroll 8
    for (int p = 0; p < NPART; p++) {
        tot += g_part[p * 128 + t];
        g_part[p * 128 + t] = 0.0f;
    }
    g_sums[t] = tot;
    __syncthreads();
    if (t < 64) {
        float mu  = g_sums[t] * invE;
        float var = fmaxf(g_sums[64 + t] * invE - mu * mu, 0.0f);
        float rstd = rsqrtf(var + 1e-5f);
        float sc = gamma[t] * rstd;
        g_scale[t] = sc;
        g_shift[t] = fmaf(-mu, sc, beta[t]);
    }
}

// ---------------- final: BN+softplus, dot w_out, edge dir, scatter-add --------
// Consumes FRAGMENT-MAJOR g_bufA with coalesced LDG.128. Thread (wb,l) dots its
// lane's share of rows r0 = blk*128+wb*16+lg and r1 = r0+8; 2-shuffle reduce
// over the 4 lq lanes; lanes lq0/lq1 finalize edges r0/r1.
__global__ void __launch_bounds__(256)
force_kernel(const float* __restrict__ w_out, const float* __restrict__ b_out,
             const float* __restrict__ pos, const float* __restrict__ nbr,
             const int* __restrict__ eidx, float* __restrict__ out, int E)
{
    __shared__ float swv[FDIM], sc[FDIM], sh[FDIM];
    int t = threadIdx.x;
    if (t < FDIM) { swv[t] = w_out[t]; sc[t] = g_scale[t]; sh[t] = g_shift[t]; }
    __syncthreads();

    const int wb = t >> 5;
    const int l  = t & 31;
    const int lq = l & 3;
    const int lg = l >> 2;
    const size_t fbase = ((size_t)blockIdx.x * 8 + wb) * 8;
    const float4* F = reinterpret_cast<const float4*>(g_bufA);

    float s0 = 0.0f, s1 = 0.0f;
    #pragma unroll
    for (int j = 0; j < 8; j++) {
        float4 v = F[(fbase + j) * 32 + l];
        int c = j * 8 + lq * 2;
        float w0 = swv[c], w1 = swv[c + 1];
        float c0s = sc[c], c0h = sh[c], c1s = sc[c + 1], c1h = sh[c + 1];
        s0 = fmaf(softplusf(fmaf(v.x, c0s, c0h)), w0, s0);
        s0 = fmaf(softplusf(fmaf(v.y, c1s, c1h)), w1, s0);
        s1 = fmaf(softplusf(fmaf(v.z, c0s, c0h)), w0, s1);
        s1 = fmaf(softplusf(fmaf(v.w, c1s, c1h)), w1, s1);
    }
    // reduce over lq lanes (xor 1, 2)
    s0 += __shfl_xor_sync(0xffffffffu, s0, 1);
    s0 += __shfl_xor_sync(0xffffffffu, s0, 2);
    s1 += __shfl_xor_sync(0xffffffffu, s1, 1);
    s1 += __shfl_xor_sync(0xffffffffu, s1, 2);

    int e = -1;
    float s = 0.0f;
    if (lq == 0)      { e = blockIdx.x * 128 + wb * 16 + lg;     s = s0; }
    else if (lq == 1) { e = blockIdx.x * 128 + wb * 16 + lg + 8; s = s1; }
    if (e >= 0 && e < E) {
        s += b_out[0];
        int jn  = eidx[e];          // source j
        int in_ = eidx[E + e];      // target i
        float dx = pos[in_ * 3 + 0] + nbr[(size_t)e * 3 + 0] - pos[jn * 3 + 0];
        float dy = pos[in_ * 3 + 1] + nbr[(size_t)e * 3 + 1] - pos[jn * 3 + 1];
        float dz = pos[in_ * 3 + 2] + nbr[(size_t)e * 3 + 2] - pos[jn * 3 + 2];
        float inv = rsqrtf(fmaf(dx, dx, fmaf(dy, dy, dz * dz)));
        float f = s * inv;
        atomicAdd(out + in_ * 3 + 0, f * dx);
        atomicAdd(out + in_ * 3 + 1, f * dy);
        atomicAdd(out + in_ * 3 + 2, f * dz);
    }
}

// ---------------- launch ----------------
extern "C" void kernel_launch(void* const* d_in, const int* in_sizes, int n_in,
                              void* d_out, int out_size)
{
    const float* edge_attr = (const float*)d_in[0];
    const float* nbr_shift = (const float*)d_in[1];
    const float* pos       = (const float*)d_in[2];
    const float* Ws        = (const float*)d_in[3];   // [3][64][64]
    const float* bs        = (const float*)d_in[4];   // [3][64]
    const float* gammas    = (const float*)d_in[5];   // [3][64]
    const float* betas     = (const float*)d_in[6];   // [3][64]
    const float* w_out     = (const float*)d_in[7];   // [64]
    const float* b_out     = (const float*)d_in[8];   // [1]
    const int*   eidx      = (const int*)d_in[9];     // [2][E] int32
    float* out = (float*)d_out;

    int E = in_sizes[0] / FDIM;     // 1,600,000
    if (E <= 0) return;
    float invE = 1.0f / (float)E;
    int gBlocks = E / 256;          // 6250 (gemm tiles)
    int fBlocks = E / 128;          // 12500 (force tiles)

    init_kernel<<<(out_size + 255) / 256, 256>>>(out, out_size);

    gemm0_kernel<<<gBlocks, 256>>>(edge_attr, Ws, bs);
    finalize_kernel<<<1, 128>>>(gammas, betas, invE);

    gemm1_kernel<<<gBlocks, 256>>>(Ws + FDIM * FDIM, bs + FDIM);
    finalize_kernel<<<1, 128>>>(gammas + FDIM, betas + FDIM, invE);

    gemm2_kernel<<<gBlocks, 256>>>(Ws + 2 * FDIM * FDIM, bs + 2 * FDIM);
    finalize_kernel<<<1, 128>>>(gammas + 2 * FDIM, betas + 2 * FDIM, invE);

    force_kernel<<<fBlocks, 256>>>(w_out, b_out, pos, nbr_shift, eidx, out, E);
}

// round 15
// speedup vs baseline: 1.4192x; 1.0176x over previous
#include <cuda_runtime.h>
#include <cuda_bf16.h>
#include <cstdint>
#include <cstddef>

#define FDIM 64
#define EMAX 1600000
#define NPART 64

// ---------------- device scratch (no allocations allowed) ----------------
// Activation buffers hold FRAGMENT-MAJOR float4s:
//   index ((blk*8 + wb)*8 + j)*32 + l  holds (y(r0,c), y(r0,c+1), y(r1,c), y(r1,c+1))
//   with blk = row/128, r0 = blk*128 + wb*16 + (l>>2), r1 = r0 + 8, c = j*8 + (l&3)*2.
__device__ float g_bufA[(size_t)EMAX * FDIM];   // 409.6 MB
__device__ float g_bufB[(size_t)EMAX * FDIM];   // 409.6 MB
__device__ float g_part[NPART * 2 * FDIM];      // partial stats buckets
__device__ __align__(16) float g_sums[2 * FDIM];
__device__ __align__(16) float g_scale[FDIM];   // gamma * rstd
__device__ __align__(16) float g_shift[FDIM];   // beta - mu * gamma * rstd

// softplus(x) = max(x,0) + log1p(exp(-|x|)); __logf(1+e) abs err < 6e-8.
__device__ __forceinline__ float softplusf(float x) {
    float e = __expf(-fabsf(x));
    return fmaxf(x, 0.0f) + __logf(1.0f + e);
}

// split (x,y) into bf16 hi pack + bf16 residual pack (x in low half)
__device__ __forceinline__ void split2(float x, float y, uint32_t& hi, uint32_t& lo) {
    __nv_bfloat16 hx = __float2bfloat16_rn(x);
    __nv_bfloat16 hy = __float2bfloat16_rn(y);
    float rx = x - __bfloat162float(hx);
    float ry = y - __bfloat162float(hy);
    __nv_bfloat162 h; h.x = hx; h.y = hy;
    __nv_bfloat162 r = __floats2bfloat162_rn(rx, ry);
    hi = *reinterpret_cast<uint32_t*>(&h);
    lo = *reinterpret_cast<uint32_t*>(&r);
}

__device__ __forceinline__ void mma_bf16(float* c, uint32_t a0, uint32_t a1,
                                         uint32_t a2, uint32_t a3,
                                         uint32_t b0, uint32_t b1) {
    asm volatile(
        "mma.sync.aligned.m16n8k16.row.col.f32.bf16.bf16.f32 "
        "{%0,%1,%2,%3}, {%4,%5,%6,%7}, {%8,%9}, {%0,%1,%2,%3};"
        : "+f"(c[0]), "+f"(c[1]), "+f"(c[2]), "+f"(c[3])
        : "r"(a0), "r"(a1), "r"(a2), "r"(a3), "r"(b0), "r"(b1));
}

// ---------------- init: zero output + partial stats ----------------
__global__ void init_kernel(float* __restrict__ out, int n) {
    int i = blockIdx.x * blockDim.x + threadIdx.x;
    if (i < n) out[i] = 0.0f;
    if (i < NPART * 2 * FDIM) g_part[i] = 0.0f;
}

// Load raw fragments for k-step sidx into dst[4]:
//   dst[2*mt+0] = (r0:k0,k0+1, r1:k0,k0+1), dst[2*mt+1] = same at k0+8.
template<bool ACT>
__device__ __forceinline__ void load_s(float4* dst, int sidx,
    const float4* __restrict__ inF, const size_t* fbase,
    const float* __restrict__ inB, int wb, int lg, int lq, int l)
{
    if (ACT) {
        dst[0] = inF[(fbase[0] + 2 * sidx) * 32 + l];
        dst[1] = inF[(fbase[0] + 2 * sidx + 1) * 32 + l];
        dst[2] = inF[(fbase[1] + 2 * sidx) * 32 + l];
        dst[3] = inF[(fbase[1] + 2 * sidx + 1) * 32 + l];
    } else {
        const int kk = 16 * sidx + 2 * lq;
        #pragma unroll
        for (int mt = 0; mt < 2; mt++) {
            const int r0 = mt * 128 + wb * 16 + lg;
            const int r1 = r0 + 8;
            float2 a = *reinterpret_cast<const float2*>(inB + (size_t)r0 * FDIM + kk);
            float2 b = *reinterpret_cast<const float2*>(inB + (size_t)r1 * FDIM + kk);
            float2 c = *reinterpret_cast<const float2*>(inB + (size_t)r0 * FDIM + kk + 8);
            float2 d = *reinterpret_cast<const float2*>(inB + (size_t)r1 * FDIM + kk + 8);
            dst[2 * mt + 0] = make_float4(a.x, a.y, b.x, b.y);
            dst[2 * mt + 1] = make_float4(c.x, c.y, d.x, d.y);
        }
    }
}

// ---------------- fused GEMM (bf16x2-split mma.sync.m16n8k16) ----------------
// CTA: 256 thr = 8 warps, tile 256 rows x 64 cols (2 m-tiles per warp), K=64.
// Software-pipelined: all 4 raw LDG.128 of step s+1 issued before step s's
// transform+mma (MLP 2 -> 4, transform covers DRAM latency). W staged once in
// smem hi/lo pre-split; one W LDS feeds 6 mmas. launch_bounds(256,2).
template<bool ACT>
__device__ __forceinline__ void gemm_body(
    const float* __restrict__ in, float* __restrict__ out,
    const float* __restrict__ W, const float* __restrict__ bias)
{
    __shared__ uint4 sW[1024];       // 16 KB: [s(4)][j(8)][l(32)] = bh0,bh1,bl0,bl1
    __shared__ float sSc[FDIM], sSh[FDIM];

    const int t  = threadIdx.x;
    const int wb = t >> 5;          // warp 0..7
    const int l  = t & 31;
    const int lq = l & 3;           // threadID_in_group
    const int lg = l >> 2;          // groupID

    if (ACT && t < 64) { sSc[t] = g_scale[t]; sSh[t] = g_shift[t]; }

    // W frags: warp wb covers n-tile j = wb, its lane slot, all 4 k-steps.
    {
        const int n = wb * 8 + lg;
        #pragma unroll
        for (int s = 0; s < 4; s++) {
            int k0 = 16 * s + 2 * lq;
            float w00 = W[k0 * 64 + n],       w01 = W[(k0 + 1) * 64 + n];
            float w10 = W[(k0 + 8) * 64 + n], w11 = W[(k0 + 9) * 64 + n];
            uint32_t bh0, bl0, bh1, bl1;
            split2(w00, w01, bh0, bl0);
            split2(w10, w11, bh1, bl1);
            sW[(s * 8 + wb) * 32 + l] = make_uint4(bh0, bh1, bl0, bl1);
        }
    }
    __syncthreads();

    const size_t rowBase = (size_t)blockIdx.x * 256;
    const float* inB = in + rowBase * FDIM;                    // row-major path
    const float4* inF = reinterpret_cast<const float4*>(in);   // frag-major path
    size_t fbase[2];                                           // 128-row layout blocks
    fbase[0] = (((size_t)blockIdx.x * 2 + 0) * 8 + wb) * 8;
    fbase[1] = (((size_t)blockIdx.x * 2 + 1) * 8 + wb) * 8;

    float acc[2][8][4];
    #pragma unroll
    for (int mt = 0; mt < 2; mt++)
        #pragma unroll
        for (int j = 0; j < 8; j++)
            #pragma unroll
            for (int c = 0; c < 4; c++) acc[mt][j][c] = 0.0f;

    float4 nf[4];
    load_s<ACT>(nf, 0, inF, fbase, inB, wb, lg, lq, l);

    #pragma unroll
    for (int s = 0; s < 4; s++) {
        float4 cf[4];
        cf[0] = nf[0]; cf[1] = nf[1]; cf[2] = nf[2]; cf[3] = nf[3];
        if (s < 3) load_s<ACT>(nf, s + 1, inF, fbase, inB, wb, lg, lq, l);  // prefetch

        const int k0 = 16 * s + 2 * lq;
        float sc0, sh0, sc1, sh1, sc8, sh8, sc9, sh9;
        if (ACT) {
            sc0 = sSc[k0];     sh0 = sSh[k0];
            sc1 = sSc[k0 + 1]; sh1 = sSh[k0 + 1];
            sc8 = sSc[k0 + 8]; sh8 = sSh[k0 + 8];
            sc9 = sSc[k0 + 9]; sh9 = sSh[k0 + 9];
        }
        uint4 ah[2], al[2];
        #pragma unroll
        for (int mt = 0; mt < 2; mt++) {
            float4 fa = cf[2 * mt], fb = cf[2 * mt + 1];
            if (ACT) {
                fa.x = softplusf(fmaf(fa.x, sc0, sh0)); fa.y = softplusf(fmaf(fa.y, sc1, sh1));
                fa.z = softplusf(fmaf(fa.z, sc0, sh0)); fa.w = softplusf(fmaf(fa.w, sc1, sh1));
                fb.x = softplusf(fmaf(fb.x, sc8, sh8)); fb.y = softplusf(fmaf(fb.y, sc9, sh9));
                fb.z = softplusf(fmaf(fb.z, sc8, sh8)); fb.w = softplusf(fmaf(fb.w, sc9, sh9));
            }
            uint32_t h0, l0, h1, l1, h2, l2, h3, l3;
            split2(fa.x, fa.y, h0, l0);   // row r0, k k0..k0+1
            split2(fa.z, fa.w, h1, l1);   // row r1, k k0..k0+1
            split2(fb.x, fb.y, h2, l2);   // row r0, k+8
            split2(fb.z, fb.w, h3, l3);   // row r1, k+8
            ah[mt] = make_uint4(h0, h1, h2, h3);
            al[mt] = make_uint4(l0, l1, l2, l3);
        }
        #pragma unroll
        for (int j = 0; j < 8; j++) {
            uint4 w = sW[(s * 8 + j) * 32 + l];
            #pragma unroll
            for (int mt = 0; mt < 2; mt++) {
                mma_bf16(acc[mt][j], ah[mt].x, ah[mt].y, ah[mt].z, ah[mt].w, w.x, w.y);
                mma_bf16(acc[mt][j], al[mt].x, al[mt].y, al[mt].z, al[mt].w, w.x, w.y);
                mma_bf16(acc[mt][j], ah[mt].x, ah[mt].y, ah[mt].z, ah[mt].w, w.z, w.w);
            }
        }
    }

    // ---- epilogue: +bias, coalesced frag-major store, column stats ----
    __syncthreads();                        // all sW reads done; reuse for stats
    float* sStats = reinterpret_cast<float*>(sW);
    if (t < 128) sStats[t] = 0.0f;

    float st1[16], st2[16];
    #pragma unroll
    for (int i = 0; i < 16; i++) { st1[i] = 0.0f; st2[i] = 0.0f; }

    float4* outF = reinterpret_cast<float4*>(out);
    #pragma unroll
    for (int mt = 0; mt < 2; mt++) {
        #pragma unroll
        for (int j = 0; j < 8; j++) {
            int c0 = j * 8 + lq * 2;
            float2 b2 = *reinterpret_cast<const float2*>(bias + c0);
            float y00 = acc[mt][j][0] + b2.x, y01 = acc[mt][j][1] + b2.y;   // row r0
            float y10 = acc[mt][j][2] + b2.x, y11 = acc[mt][j][3] + b2.y;   // row r1
            st1[j * 2]     += y00 + y10;
            st1[j * 2 + 1] += y01 + y11;
            st2[j * 2]     = fmaf(y00, y00, fmaf(y10, y10, st2[j * 2]));
            st2[j * 2 + 1] = fmaf(y01, y01, fmaf(y11, y11, st2[j * 2 + 1]));
            outF[(fbase[mt] + j) * 32 + l] = make_float4(y00, y01, y10, y11);
        }
    }
    // reduce over the 8 lanes sharing lq (xor 4, 8, 16)
    #pragma unroll
    for (int d = 4; d <= 16; d <<= 1) {
        #pragma unroll
        for (int i = 0; i < 16; i++) {
            st1[i] += __shfl_xor_sync(0xffffffffu, st1[i], d);
            st2[i] += __shfl_xor_sync(0xffffffffu, st2[i], d);
        }
    }
    __syncthreads();                        // sStats zeroed before atomics
    if (lg == 0) {   // lanes 0..3 hold column sums
        #pragma unroll
        for (int j = 0; j < 8; j++) {
            int c0 = j * 8 + lq * 2;
            atomicAdd(&sStats[c0],          st1[j * 2]);
            atomicAdd(&sStats[c0 + 1],      st1[j * 2 + 1]);
            atomicAdd(&sStats[64 + c0],     st2[j * 2]);
            atomicAdd(&sStats[64 + c0 + 1], st2[j * 2 + 1]);
        }
    }
    __syncthreads();
    if (t < 128)
        atomicAdd(&g_part[(blockIdx.x & (NPART - 1)) * 128 + t], sStats[t]);
}

__global__ void __launch_bounds__(256, 2)
gemm0_kernel(const float* __restrict__ in, const float* __restrict__ W,
             const float* __restrict__ bias) {
    gemm_body<false>(in, g_bufA, W, bias);
}
__global__ void __launch_bounds__(256, 2)
gemm1_kernel(const float* __restrict__ W, const float* __restrict__ bias) {
    gemm_body<true>(g_bufA, g_bufB, W, bias);
}
__global__ void __launch_bounds__(256, 2)
gemm2_kernel(const float* __restrict__ W, const float* __restrict__ bias) {
    gemm_body<true>(g_bufB, g_bufA, W, bias);
}

// ---------------- finalize: reduce partials -> scale/shift; re-zero partials ----
__global__ void finalize_kernel(const float* __restrict__ gamma,
                                const float* __restrict__ beta, float invE) {
    int t = threadIdx.x;   // 128 threads
    float tot = 0.0f;
    #pragma unroll 8
    for (int p = 0; p < NPART; p++) {
        tot += g_part[p * 128 + t];
        g_part[p * 128 + t] = 0.0f;
    }
    g_sums[t] = tot;
    __syncthreads();
    if (t < 64) {
        float mu  = g_sums[t] * invE;
        float var = fmaxf(g_sums[64 + t] * invE - mu * mu, 0.0f);
        float rstd = rsqrtf(var + 1e-5f);
        float sc = gamma[t] * rstd;
        g_scale[t] = sc;
        g_shift[t] = fmaf(-mu, sc, beta[t]);
    }
}

// ---------------- final: BN+softplus, dot w_out, edge dir, scatter-add --------
// Consumes FRAGMENT-MAJOR g_bufA with coalesced LDG.128. Thread (wb,l) dots its
// lane's share of rows r0 = blk*128+wb*16+lg and r1 = r0+8; 2-shuffle reduce
// over the 4 lq lanes; lanes lq0/lq1 finalize edges r0/r1.
__global__ void __launch_bounds__(256)
force_kernel(const float* __restrict__ w_out, const float* __restrict__ b_out,
             const float* __restrict__ pos, const float* __restrict__ nbr,
             const int* __restrict__ eidx, float* __restrict__ out, int E)
{
    __shared__ float swv[FDIM], sc[FDIM], sh[FDIM];
    int t = threadIdx.x;
    if (t < FDIM) { swv[t] = w_out[t]; sc[t] = g_scale[t]; sh[t] = g_shift[t]; }
    __syncthreads();

    const int wb = t >> 5;
    const int l  = t & 31;
    const int lq = l & 3;
    const int lg = l >> 2;
    const size_t fbase = ((size_t)blockIdx.x * 8 + wb) * 8;
    const float4* F = reinterpret_cast<const float4*>(g_bufA);

    float s0 = 0.0f, s1 = 0.0f;
    #pragma unroll
    for (int j = 0; j < 8; j++) {
        float4 v = F[(fbase + j) * 32 + l];
        int c = j * 8 + lq * 2;
        float w0 = swv[c], w1 = swv[c + 1];
        float c0s = sc[c], c0h = sh[c], c1s = sc[c + 1], c1h = sh[c + 1];
        s0 = fmaf(softplusf(fmaf(v.x, c0s, c0h)), w0, s0);
        s0 = fmaf(softplusf(fmaf(v.y, c1s, c1h)), w1, s0);
        s1 = fmaf(softplusf(fmaf(v.z, c0s, c0h)), w0, s1);
        s1 = fmaf(softplusf(fmaf(v.w, c1s, c1h)), w1, s1);
    }
    // reduce over lq lanes (xor 1, 2)
    s0 += __shfl_xor_sync(0xffffffffu, s0, 1);
    s0 += __shfl_xor_sync(0xffffffffu, s0, 2);
    s1 += __shfl_xor_sync(0xffffffffu, s1, 1);
    s1 += __shfl_xor_sync(0xffffffffu, s1, 2);

    int e = -1;
    float s = 0.0f;
    if (lq == 0)      { e = blockIdx.x * 128 + wb * 16 + lg;     s = s0; }
    else if (lq == 1) { e = blockIdx.x * 128 + wb * 16 + lg + 8; s = s1; }
    if (e >= 0 && e < E) {
        s += b_out[0];
        int jn  = eidx[e];          // source j
        int in_ = eidx[E + e];      // target i
        float dx = pos[in_ * 3 + 0] + nbr[(size_t)e * 3 + 0] - pos[jn * 3 + 0];
        float dy = pos[in_ * 3 + 1] + nbr[(size_t)e * 3 + 1] - pos[jn * 3 + 1];
        float dz = pos[in_ * 3 + 2] + nbr[(size_t)e * 3 + 2] - pos[jn * 3 + 2];
        float inv = rsqrtf(fmaf(dx, dx, fmaf(dy, dy, dz * dz)));
        float f = s * inv;
        atomicAdd(out + in_ * 3 + 0, f * dx);
        atomicAdd(out + in_ * 3 + 1, f * dy);
        atomicAdd(out + in_ * 3 + 2, f * dz);
    }
}

// ---------------- launch ----------------
extern "C" void kernel_launch(void* const* d_in, const int* in_sizes, int n_in,
                              void* d_out, int out_size)
{
    const float* edge_attr = (const float*)d_in[0];
    const float* nbr_shift = (const float*)d_in[1];
    const float* pos       = (const float*)d_in[2];
    const float* Ws        = (const float*)d_in[3];   // [3][64][64]
    const float* bs        = (const float*)d_in[4];   // [3][64]
    const float* gammas    = (const float*)d_in[5];   // [3][64]
    const float* betas     = (const float*)d_in[6];   // [3][64]
    const float* w_out     = (const float*)d_in[7];   // [64]
    const float* b_out     = (const float*)d_in[8];   // [1]
    const int*   eidx      = (const int*)d_in[9];     // [2][E] int32
    float* out = (float*)d_out;

    int E = in_sizes[0] / FDIM;     // 1,600,000
    if (E <= 0) return;
    float invE = 1.0f / (float)E;
    int gBlocks = E / 256;          // 6250 (gemm tiles)
    int fBlocks = E / 128;          // 12500 (force tiles)

    init_kernel<<<(out_size + 255) / 256, 256>>>(out, out_size);

    gemm0_kernel<<<gBlocks, 256>>>(edge_attr, Ws, bs);
    finalize_kernel<<<1, 128>>>(gammas, betas, invE);

    gemm1_kernel<<<gBlocks, 256>>>(Ws + FDIM * FDIM, bs + FDIM);
    finalize_kernel<<<1, 128>>>(gammas + FDIM, betas + FDIM, invE);

    gemm2_kernel<<<gBlocks, 256>>>(Ws + 2 * FDIM * FDIM, bs + 2 * FDIM);
    finalize_kernel<<<1, 128>>>(gammas + 2 * FDIM, betas + 2 * FDIM, invE);

    force_kernel<<<fBlocks, 256>>>(w_out, b_out, pos, nbr_shift, eidx, out, E);
}